// round 13
// baseline (speedup 1.0000x reference)
#include <cuda_runtime.h>
#include <cuda_fp16.h>
#include <mma.h>
#include <cstdint>

using namespace nvcuda;

#define SEQ    512
#define INSZ   4096
#define HID    2048
#define OUTSZ  4096
#define STEPS  30
#define G3     6144   // 3*HID

#define NB     128    // persistent CTAs (1/SM, guaranteed co-resident)
#define NT     512    // 16 warps
#define NWARP  16
#define UPB    16     // hidden units per block   (2048/128)
#define RPB    48     // gate rows per block      (3*UPB)
#define ORPB   32     // output rows per block    (4096/128)
#define GH_STR 17     // padded stride for gh_part rows (bank-conflict-free)

// ---------------- device globals (static scratch; no runtime allocation) ----
__device__ float               g_GI[SEQ * G3];        // Wih@x (NO bias)
__device__ __half              g_Xh[SEQ * INSZ];      // fp16 input
__device__ __half              g_Wh[G3 * INSZ];       // fp16 enc_Wih
__device__ __half              g_Woh[OUTSZ * HID];    // fp16 W_out
__device__ __half              g_hdat[2][NB * UPB];   // fp16 h slots (32B/CTA)
__device__ unsigned            g_flagp[NB * 8];       // h flags, 32B padded
__device__ ulonglong2          g_pdat[2][NB];         // (pack, lsum-bits) slots
__device__ unsigned            g_flag2p[NB * 8];      // pack flags, 32B padded

// ---------------- helpers ---------------------------------------------------
__device__ __forceinline__ float warp_sum(float v) {
#pragma unroll
    for (int o = 16; o; o >>= 1) v += __shfl_xor_sync(0xffffffffu, v, o);
    return v;
}
__device__ __forceinline__ float sigmoidf_(float x) {
    return 1.0f / (1.0f + expf(-x));
}
__device__ __forceinline__ unsigned f2sortable(float v) {
    unsigned sb = __float_as_uint(v);
    return (sb & 0x80000000u) ? ~sb : (sb | 0x80000000u);
}
__device__ __forceinline__ float sortable2f(unsigned s) {
    return __uint_as_float((s & 0x80000000u) ? (s & 0x7FFFFFFFu) : ~s);
}
__device__ __forceinline__ unsigned ld_flag(const unsigned* p) {
    unsigned f;
    asm volatile("ld.relaxed.gpu.global.u32 %0, [%1];" : "=r"(f) : "l"(p) : "memory");
    return f;
}
__device__ __forceinline__ void st_flag(unsigned* p, unsigned v) {
    asm volatile("st.relaxed.gpu.global.u32 [%0], %1;" :: "l"(p), "r"(v) : "memory");
}
__device__ __forceinline__ void fence_gpu() {
    asm volatile("fence.acq_rel.gpu;" ::: "memory");
}

// One-time weight load + re-layout into chunked SMEM format.
// Warp w owns columns [w*128, w*128+128) of ALL 48 gate rows.
// SMEM layout (uint4 = 16B = 8 halfs):
//   wsu4[ ((w*6 + g)*4 + c)*32 + lane ]  holds
//   row r48 = g*8 + (lane&7),  cols w*128 + (lane>>3)*32 + c*8 .. +8
// -> every LDS.128 is a contiguous 512B warp access (conflict-free).
__device__ void load_w48(const float* __restrict__ W, __half* ws, int bid,
                         int warp, int lane) {
    int r8 = lane & 7, cg = lane >> 3;
    uint4* wsu = (uint4*)ws;
#pragma unroll
    for (int g = 0; g < 6; g++) {
        int r48  = g * 8 + r8;
        int grow = (r48 >> 4) * HID + bid * UPB + (r48 & 15);
        const float4* src =
            (const float4*)(W + (size_t)grow * HID + warp * 128 + cg * 32);
#pragma unroll
        for (int c = 0; c < 4; c++) {
            float4 a = __ldg(&src[c * 2]);
            float4 b = __ldg(&src[c * 2 + 1]);
            uint4 h4;
            *(__half2*)&h4.x = __floats2half2_rn(a.x, a.y);
            *(__half2*)&h4.y = __floats2half2_rn(a.z, a.w);
            *(__half2*)&h4.z = __floats2half2_rn(b.x, b.y);
            *(__half2*)&h4.w = __floats2half2_rn(b.z, b.w);
            wsu[((warp * 6 + g) * 4 + c) * 32 + lane] = h4;
        }
    }
}

// Column-partial matvec: warp computes all 48 rows over its 128 columns.
// H[c] = 8 halfs of h for cols (lane>>3)*32 + c*8 (within warp's 128).
// Partials (fp32, incl lane+cg reduce) -> ghp[r48*GH_STR + warp].
__device__ __forceinline__ void mv_partial(const __half* __restrict__ ws,
                                           int warp, int lane,
                                           const uint4* H, float* ghp) {
    int r8 = lane & 7;
    const uint4* wsu = (const uint4*)ws;
#pragma unroll
    for (int g = 0; g < 6; g++) {
        int base = ((warp * 6 + g) * 4) * 32 + lane;
        uint4 w0 = wsu[base];
        uint4 w1 = wsu[base + 32];
        uint4 w2 = wsu[base + 64];
        uint4 w3 = wsu[base + 96];
        __half2 s0 = __hmul2(*(__half2*)&w0.x, *(const __half2*)&H[0].x);
        s0 = __hfma2(*(__half2*)&w0.y, *(const __half2*)&H[0].y, s0);
        s0 = __hfma2(*(__half2*)&w0.z, *(const __half2*)&H[0].z, s0);
        s0 = __hfma2(*(__half2*)&w0.w, *(const __half2*)&H[0].w, s0);
        s0 = __hfma2(*(__half2*)&w1.x, *(const __half2*)&H[1].x, s0);
        s0 = __hfma2(*(__half2*)&w1.y, *(const __half2*)&H[1].y, s0);
        s0 = __hfma2(*(__half2*)&w1.z, *(const __half2*)&H[1].z, s0);
        s0 = __hfma2(*(__half2*)&w1.w, *(const __half2*)&H[1].w, s0);
        __half2 s1 = __hmul2(*(__half2*)&w2.x, *(const __half2*)&H[2].x);
        s1 = __hfma2(*(__half2*)&w2.y, *(const __half2*)&H[2].y, s1);
        s1 = __hfma2(*(__half2*)&w2.z, *(const __half2*)&H[2].z, s1);
        s1 = __hfma2(*(__half2*)&w2.w, *(const __half2*)&H[2].w, s1);
        s1 = __hfma2(*(__half2*)&w3.x, *(const __half2*)&H[3].x, s1);
        s1 = __hfma2(*(__half2*)&w3.y, *(const __half2*)&H[3].y, s1);
        s1 = __hfma2(*(__half2*)&w3.z, *(const __half2*)&H[3].z, s1);
        s1 = __hfma2(*(__half2*)&w3.w, *(const __half2*)&H[3].w, s1);
        float2 f0 = __half22float2(s0);
        float2 f1 = __half22float2(s1);
        float acc = (f0.x + f0.y) + (f1.x + f1.y);
        acc += __shfl_xor_sync(0xffffffffu, acc, 8);
        acc += __shfl_xor_sync(0xffffffffu, acc, 16);
        if (lane < 8) ghp[(g * 8 + r8) * GH_STR + warp] = acc;
    }
}

// Poll own 8 slots' flags >= j, acquire, load 64B of fp16 h into registers.
__device__ __forceinline__ void wait_load_h(int warp, int lane, unsigned base,
                                            unsigned j, uint4* H) {
    if (lane < 8) {
        const unsigned* fp = &g_flagp[(warp * 8 + lane) * 8];
        while (ld_flag(fp) - base < j) { }
    }
    __syncwarp();
    fence_gpu();
    const uint4* hp = (const uint4*)((const char*)g_hdat[j & 1]
                                     + warp * 256 + (lane >> 3) * 64);
#pragma unroll
    for (int c = 0; c < 4; c++) H[c] = __ldcg(hp + c);
}

// ---------------- fp32 -> fp16 converters -----------------------------------
__global__ void __launch_bounds__(256) conv_x_kernel(const float* __restrict__ src) {
    int i = blockIdx.x * blockDim.x + threadIdx.x;   // float4 index
    if (i < SEQ * INSZ / 4) {
        float4 v = __ldg((const float4*)src + i);
        union { __half2 h[2]; uint2 u; } cv;
        cv.h[0] = __floats2half2_rn(v.x, v.y);
        cv.h[1] = __floats2half2_rn(v.z, v.w);
        ((uint2*)g_Xh)[i] = cv.u;
    }
}
__global__ void __launch_bounds__(256) conv_w_kernel(const float* __restrict__ src) {
    int i = blockIdx.x * blockDim.x + threadIdx.x;
    if (i < G3 * INSZ / 4) {
        float4 v = __ldg((const float4*)src + i);
        union { __half2 h[2]; uint2 u; } cv;
        cv.h[0] = __floats2half2_rn(v.x, v.y);
        cv.h[1] = __floats2half2_rn(v.z, v.w);
        ((uint2*)g_Wh)[i] = cv.u;
    }
}
__global__ void __launch_bounds__(256) conv_wout_kernel(const float* __restrict__ src) {
    int i = blockIdx.x * blockDim.x + threadIdx.x;
    if (i < OUTSZ * HID / 4) {
        float4 v = __ldg((const float4*)src + i);
        union { __half2 h[2]; uint2 u; } cv;
        cv.h[0] = __floats2half2_rn(v.x, v.y);
        cv.h[1] = __floats2half2_rn(v.z, v.w);
        ((uint2*)g_Woh)[i] = cv.u;
    }
}

// ---------------- kernel 1: GI = X @ Wih^T (tensor cores, fp32 accum) -------
#define KC 32
__global__ void __launch_bounds__(256) gemm_wmma_kernel() {
    __shared__ __half As[128][KC + 8];
    __shared__ __half Bs[128][KC + 8];

    int m0 = blockIdx.y * 128, n0 = blockIdx.x * 128;
    int t = threadIdx.x;
    int wid = t >> 5;
    int wm = wid & 1, wn = wid >> 1;     // warp tile: 64(M) x 32(N)

    wmma::fragment<wmma::accumulator, 16, 16, 16, float> c[4][2];
#pragma unroll
    for (int i = 0; i < 4; i++)
#pragma unroll
        for (int j = 0; j < 2; j++) wmma::fill_fragment(c[i][j], 0.f);

    int lrow = t >> 1;
    int lseg = (t & 1) * 16;

    for (int k0 = 0; k0 < INSZ; k0 += KC) {
        const uint4* ap = (const uint4*)(g_Xh + (size_t)(m0 + lrow) * INSZ + k0 + lseg);
        const uint4* bp = (const uint4*)(g_Wh + (size_t)(n0 + lrow) * INSZ + k0 + lseg);
        uint4 a0 = ap[0], a1 = ap[1];
        uint4 b0 = bp[0], b1 = bp[1];
        __syncthreads();
        *(uint4*)&As[lrow][lseg]     = a0;
        *(uint4*)&As[lrow][lseg + 8] = a1;
        *(uint4*)&Bs[lrow][lseg]     = b0;
        *(uint4*)&Bs[lrow][lseg + 8] = b1;
        __syncthreads();
#pragma unroll
        for (int kk = 0; kk < KC; kk += 16) {
            wmma::fragment<wmma::matrix_a, 16, 16, 16, __half, wmma::row_major> af[4];
            wmma::fragment<wmma::matrix_b, 16, 16, 16, __half, wmma::col_major> bf[2];
#pragma unroll
            for (int i = 0; i < 4; i++)
                wmma::load_matrix_sync(af[i], &As[wm * 64 + i * 16][kk], KC + 8);
#pragma unroll
            for (int j = 0; j < 2; j++)
                wmma::load_matrix_sync(bf[j], &Bs[wn * 32 + j * 16][kk], KC + 8);
#pragma unroll
            for (int i = 0; i < 4; i++)
#pragma unroll
                for (int j = 0; j < 2; j++)
                    wmma::mma_sync(c[i][j], af[i], bf[j], c[i][j]);
        }
    }
#pragma unroll
    for (int i = 0; i < 4; i++)
#pragma unroll
        for (int j = 0; j < 2; j++)
            wmma::store_matrix_sync(
                &g_GI[(size_t)(m0 + wm * 64 + i * 16) * G3 + n0 + wn * 32 + j * 16],
                c[i][j], G3, wmma::mem_row_major);
}

// ---------------- kernel 2: persistent encoder + decoder --------------------
__global__ void __launch_bounds__(NT, 1) rnn_kernel(
    const float* __restrict__ enc_Whh, const float* __restrict__ enc_bih,
    const float* __restrict__ enc_bhh,
    const float* __restrict__ dec_Wih, const float* __restrict__ dec_Whh,
    const float* __restrict__ dec_bih, const float* __restrict__ dec_bhh,
    const float* __restrict__ b_out,
    float* __restrict__ out) {

    extern __shared__ char dyn[];
    __half* ws     = (__half*)dyn;                          // 192KB weights
    __half* hstage = (__half*)(dyn + RPB * HID * sizeof(__half));  // 4KB

    __shared__ float gh_part[2][RPB * GH_STR];   // double-buffered partials
    __shared__ float bhh_s[RPB];
    __shared__ float bih_s[RPB];
    __shared__ float ls[ORPB];
    __shared__ float red_s[3];                   // gmax, lse, idx-as-bits

    int bid = blockIdx.x, tid = threadIdx.x;
    int warp = tid >> 5, lane = tid & 31;
    unsigned base  = ld_flag(&g_flagp[bid * 8]);    // stable at launch start
    unsigned base2 = ld_flag(&g_flag2p[bid * 8]);

    // one-time: encoder weights -> SMEM (each warp its own slice); biases
    load_w48(enc_Whh, ws, bid, warp, lane);
    if (tid < RPB) {
        int grow = (tid >> 4) * HID + bid * UPB + (tid & 15);
        bhh_s[tid] = enc_bhh[grow];
        bih_s[tid] = enc_bih[grow];
    }

    float h_reg = 0.f;                  // lane u<16 of warp 0 owns h[bid*16+u]
    unsigned j = 1;

    // publish initial h = 0 with flag j=1
    if (warp == 0) {
        if (lane < UPB) g_hdat[1][bid * UPB + lane] = __float2half(0.f);
        __syncwarp();
        if (lane == 0) { fence_gpu(); st_flag(&g_flagp[bid * 8], base + 1); }
    }

    // ---------------- encoder: 512 sequential GRU steps ----------------
    for (int t = 0; t < SEQ; t++) {
        float gi0 = 0.f, gi1 = 0.f, gi2 = 0.f;
        if (warp == 0 && lane < UPB) {
            const float* gi = g_GI + (size_t)t * G3 + bid * UPB + lane;
            gi0 = __ldg(gi); gi1 = __ldg(gi + HID); gi2 = __ldg(gi + 2 * HID);
        }
        uint4 H[4];
        wait_load_h(warp, lane, base, j, H);
        mv_partial(ws, warp, lane, H, gh_part[j & 1]);
        __syncthreads();
        if (warp == 0) {
            const float* gp = gh_part[j & 1];
            float a = 0.f, b = 0.f;
#pragma unroll
            for (int w2 = 0; w2 < NWARP; w2++) a += gp[lane * GH_STR + w2];
            if (lane < UPB) {
#pragma unroll
                for (int w2 = 0; w2 < NWARP; w2++)
                    b += gp[(lane + 32) * GH_STR + w2];
            }
            a += bhh_s[lane];
            float az = __shfl_sync(0xffffffffu, a, (lane & 15) + 16);
            if (lane < UPB) {
                b += bhh_s[lane + 32];
                float r = sigmoidf_(gi0 + bih_s[lane]      + a);
                float z = sigmoidf_(gi1 + bih_s[16 + lane] + az);
                float n = tanhf(    gi2 + bih_s[32 + lane] + r * b);
                h_reg = (1.f - z) * n + z * h_reg;
                g_hdat[(j + 1) & 1][bid * UPB + lane] = __float2half(h_reg);
            }
            __syncwarp();
            if (lane == 0) { fence_gpu(); st_flag(&g_flagp[bid * 8], base + j + 1); }
        }
        j++;
    }

    // ---------------- decoder: swap weights (own slice each warp) ----------
    __syncthreads();                    // warp0's last reduce done before bhh swap
    load_w48(dec_Whh, ws, bid, warp, lane);
    if (tid < RPB) {
        int grow = (tid >> 4) * HID + bid * UPB + (tid & 15);
        bhh_s[tid] = dec_bhh[grow];
    }

    int prev_idx = -1;     // first x is the zero vector
    for (int s = 0; s < STEPS; s++) {
        float gi0 = 0.f, gi1 = 0.f, gi2 = 0.f;
        if (warp == 0 && lane < UPB) {
            int u = bid * UPB + lane;
            gi0 = dec_bih[u];
            gi1 = dec_bih[HID + u];
            gi2 = dec_bih[2 * HID + u];
            if (prev_idx >= 0) {
                gi0 += __ldg(&dec_Wih[(size_t)u * INSZ + prev_idx]);
                gi1 += __ldg(&dec_Wih[(size_t)(HID + u) * INSZ + prev_idx]);
                gi2 += __ldg(&dec_Wih[(size_t)(2 * HID + u) * INSZ + prev_idx]);
            }
        }
        uint4 H[4];
        wait_load_h(warp, lane, base, j, H);
        mv_partial(ws, warp, lane, H, gh_part[j & 1]);
        __syncthreads();
        if (warp == 0) {
            const float* gp = gh_part[j & 1];
            float a = 0.f, b = 0.f;
#pragma unroll
            for (int w2 = 0; w2 < NWARP; w2++) a += gp[lane * GH_STR + w2];
            if (lane < UPB) {
#pragma unroll
                for (int w2 = 0; w2 < NWARP; w2++)
                    b += gp[(lane + 32) * GH_STR + w2];
            }
            a += bhh_s[lane];
            float az = __shfl_sync(0xffffffffu, a, (lane & 15) + 16);
            if (lane < UPB) {
                b += bhh_s[lane + 32];
                float r = sigmoidf_(gi0 + a);
                float z = sigmoidf_(gi1 + az);
                float n = tanhf(    gi2 + r * b);
                h_reg = (1.f - z) * n + z * h_reg;
                g_hdat[(j + 1) & 1][bid * UPB + lane] = __float2half(h_reg);
            }
            __syncwarp();
            if (lane == 0) { fence_gpu(); st_flag(&g_flagp[bid * 8], base + j + 1); }
        }
        j++;

        // stage full h^(new) (fp16) into SMEM for the logits GEMV
        if (lane < 8) {
            const unsigned* fp = &g_flagp[(warp * 8 + lane) * 8];
            while (ld_flag(fp) - base < j) { }
        }
        __syncwarp();
        fence_gpu();
        {
            uint2 v = __ldcg((const uint2*)((const char*)g_hdat[j & 1]
                                            + warp * 256 + lane * 8));
            *(uint2*)((char*)hstage + warp * 256 + lane * 8) = v;
        }
        __syncthreads();

        // logits: 16 warps x 2 rows of fp16 W_out against SMEM h
        {
            const __half2* hp = (const __half2*)hstage;
            uint4 hreg[8];
#pragma unroll
            for (int c = 0; c < 8; c++)
                hreg[c] = *(const uint4*)(hp + (c * 32 + lane) * 4);
#pragma unroll
            for (int rr = 0; rr < 2; rr++) {
                int rl = warp * 2 + rr;
                int grow = bid * ORPB + rl;
                const uint4* wrow = (const uint4*)(g_Woh + (size_t)grow * HID);
                float acc = 0.f;
#pragma unroll
                for (int c = 0; c < 8; c++) {
                    uint4 w = __ldg(&wrow[lane + c * 32]);
                    __half2 sh = __hmul2(*(__half2*)&w.x, *(__half2*)&hreg[c].x);
                    sh = __hfma2(*(__half2*)&w.y, *(__half2*)&hreg[c].y, sh);
                    sh = __hfma2(*(__half2*)&w.z, *(__half2*)&hreg[c].z, sh);
                    sh = __hfma2(*(__half2*)&w.w, *(__half2*)&hreg[c].w, sh);
                    float2 f = __half22float2(sh);
                    acc += f.x + f.y;
                }
                acc = warp_sum(acc);
                if (lane == 0) ls[rl] = acc + b_out[grow];
            }
        }
        __syncthreads();                // ls ready

        // warp 0: local (max,argmax,sumexp) -> slot; poll all; reduce
        if (warp == 0) {
            float v = ls[lane];
            unsigned long long pack =
                ((unsigned long long)f2sortable(v) << 32) |
                (unsigned long long)(0xFFFFFFFFu - (unsigned)(bid * ORPB + lane));
#pragma unroll
            for (int o = 16; o; o >>= 1) {
                unsigned long long other = __shfl_xor_sync(0xffffffffu, pack, o);
                pack = other > pack ? other : pack;
            }
            float lmax = sortable2f((unsigned)(pack >> 32));
            float e = warp_sum(expf(v - lmax));
            unsigned s1 = s + 1;
            if (lane == 0) {
                ulonglong2 slot;
                slot.x = pack;
                slot.y = (unsigned long long)__float_as_uint(e);
                __stcg(&g_pdat[s1 & 1][bid], slot);
                fence_gpu();
                st_flag(&g_flag2p[bid * 8], base2 + s1);
            }
            {
                const unsigned* fp0 = &g_flag2p[lane * 8];
                const unsigned* fp1 = &g_flag2p[(lane + 32) * 8];
                const unsigned* fp2 = &g_flag2p[(lane + 64) * 8];
                const unsigned* fp3 = &g_flag2p[(lane + 96) * 8];
                while (ld_flag(fp0) - base2 < s1) { }
                while (ld_flag(fp1) - base2 < s1) { }
                while (ld_flag(fp2) - base2 < s1) { }
                while (ld_flag(fp3) - base2 < s1) { }
                fence_gpu();
                unsigned long long pk[4];
                float lsm[4];
#pragma unroll
                for (int i = 0; i < 4; i++) {
                    ulonglong2 sl = __ldcg(&g_pdat[s1 & 1][lane + i * 32]);
                    pk[i]  = sl.x;
                    lsm[i] = __uint_as_float((unsigned)sl.y);
                }
                unsigned long long m = pk[0];
#pragma unroll
                for (int i = 1; i < 4; i++) m = pk[i] > m ? pk[i] : m;
#pragma unroll
                for (int o = 16; o; o >>= 1) {
                    unsigned long long other = __shfl_xor_sync(0xffffffffu, m, o);
                    m = other > m ? other : m;
                }
                float gmax = sortable2f((unsigned)(m >> 32));
                float part = 0.f;
#pragma unroll
                for (int i = 0; i < 4; i++)
                    part += lsm[i] * expf(sortable2f((unsigned)(pk[i] >> 32)) - gmax);
                part = warp_sum(part);
                if (lane == 0) {
                    red_s[0] = gmax;
                    red_s[1] = logf(part);
                    red_s[2] = __uint_as_float(
                        0xFFFFFFFFu - (unsigned)(m & 0xFFFFFFFFull));
                }
            }
        }
        __syncthreads();                // red_s ready
        float gmax = red_s[0], lse = red_s[1];
        prev_idx = (int)__float_as_uint(red_s[2]);
        if (tid < ORPB)
            out[(size_t)s * OUTSZ + bid * ORPB + tid] = ls[tid] - gmax - lse;
    }
}

// ---------------- launch ----------------------------------------------------
extern "C" void kernel_launch(void* const* d_in, const int* in_sizes, int n_in,
                              void* d_out, int out_size) {
    const float* input   = (const float*)d_in[0];
    const float* enc_Wih = (const float*)d_in[1];
    const float* enc_Whh = (const float*)d_in[2];
    const float* enc_bih = (const float*)d_in[3];
    const float* enc_bhh = (const float*)d_in[4];
    const float* dec_Wih = (const float*)d_in[5];
    const float* dec_Whh = (const float*)d_in[6];
    const float* dec_bih = (const float*)d_in[7];
    const float* dec_bhh = (const float*)d_in[8];
    const float* W_out   = (const float*)d_in[9];
    const float* b_out   = (const float*)d_in[10];
    float* out = (float*)d_out;

    static const int kDynSmem = RPB * HID * sizeof(__half)   // weights 192KB
                              + HID * sizeof(__half);        // h stage 4KB
    cudaFuncSetAttribute(rnn_kernel,
                         cudaFuncAttributeMaxDynamicSharedMemorySize, kDynSmem);

    conv_x_kernel<<<(SEQ * INSZ / 4 + 255) / 256, 256>>>(input);
    conv_w_kernel<<<(G3 * INSZ / 4 + 255) / 256, 256>>>(enc_Wih);
    conv_wout_kernel<<<(OUTSZ * HID / 4 + 255) / 256, 256>>>(W_out);

    dim3 g1(G3 / 128, SEQ / 128);   // 48 x 4
    gemm_wmma_kernel<<<g1, 256>>>();

    rnn_kernel<<<NB, NT, kDynSmem>>>(enc_Whh, enc_bih, enc_bhh,
                                     dec_Wih, dec_Whh, dec_bih, dec_bhh,
                                     b_out, out);
}

// round 14
// speedup vs baseline: 2.1638x; 2.1638x over previous
#include <cuda_runtime.h>
#include <cuda_fp16.h>
#include <mma.h>
#include <cstdint>

using namespace nvcuda;

#define SEQ    512
#define INSZ   4096
#define HID    2048
#define OUTSZ  4096
#define STEPS  30
#define G3     6144   // 3*HID

#define NB     128    // persistent CTAs (1/SM, guaranteed co-resident)
#define NT     512    // 16 warps
#define NWARP  16
#define UPB    16     // hidden units per block   (2048/128)
#define RPB    48     // gate rows per block      (3*UPB)
#define RPW    3      // rows per warp            (48/16)
#define ORPB   32     // output rows per block    (4096/128)

// ---------------- device globals (static scratch; no runtime allocation) ----
__device__ float   g_GI[SEQ * G3];        // Wih@x (NO bias)
__device__ __half  g_Xh[SEQ * INSZ];      // fp16 input
__device__ __half  g_Wh[G3 * INSZ];       // fp16 enc_Wih
__device__ __half  g_Woh[OUTSZ * HID];    // fp16 W_out
// Self-synchronizing h slots: per CTA, per parity, 4x16B chunks (3 used).
// Chunk c = { h[6c..6c+1], h[6c+2..6c+3], h[6c+4..6c+5] (fp16 pairs), counter }.
// A 16B relaxed store/load is one L2 sector transaction: counter match => data.
__device__ uint4   g_hslot[2][NB][4];
// Decoder (argmax|sumexp) slots: { pack_lo, pack_hi, lsum_bits, counter }.
__device__ uint4   g_pslot[2][NB];

// ---------------- helpers ---------------------------------------------------
__device__ __forceinline__ float warp_sum(float v) {
#pragma unroll
    for (int o = 16; o; o >>= 1) v += __shfl_xor_sync(0xffffffffu, v, o);
    return v;
}
__device__ __forceinline__ float sigmoidf_(float x) {
    return 1.0f / (1.0f + expf(-x));
}
__device__ __forceinline__ unsigned f2sortable(float v) {
    unsigned sb = __float_as_uint(v);
    return (sb & 0x80000000u) ? ~sb : (sb | 0x80000000u);
}
__device__ __forceinline__ float sortable2f(unsigned s) {
    return __uint_as_float((s & 0x80000000u) ? (s & 0x7FFFFFFFu) : ~s);
}
__device__ __forceinline__ uint4 ld_rlx4(const uint4* p) {
    uint4 v;
    asm volatile("ld.relaxed.gpu.global.v4.u32 {%0,%1,%2,%3}, [%4];"
                 : "=r"(v.x), "=r"(v.y), "=r"(v.z), "=r"(v.w) : "l"(p) : "memory");
    return v;
}
__device__ __forceinline__ void st_rlx4(uint4* p, uint4 v) {
    asm volatile("st.relaxed.gpu.global.v4.u32 [%0], {%1,%2,%3,%4};"
                 :: "l"(p), "r"(v.x), "r"(v.y), "r"(v.z), "r"(v.w) : "memory");
}
__device__ __forceinline__ unsigned later_u(unsigned a, unsigned b) {
    return ((int)(a - b) >= 0) ? a : b;   // handles wraparound
}

// Publish 16 h values (half bits in lanes 0..15) + counter, 3 chunks.
// All 32 lanes run the shuffles; lanes 0..2 store their chunk.
__device__ __forceinline__ void publish_h(int bid, int lane, unsigned hb,
                                          unsigned cnt, int buf) {
    unsigned w0 = 0, w1 = 0, w2 = 0;
#pragma unroll
    for (int k = 0; k < 6; k++) {
        unsigned t = __shfl_sync(0xffffffffu, hb, (lane * 6 + k) & 15);
        if (k < 2)      w0 |= (t & 0xffffu) << (16 * k);
        else if (k < 4) w1 |= (t & 0xffffu) << (16 * (k - 2));
        else            w2 |= (t & 0xffffu) << (16 * (k - 4));
    }
    if (lane < 3) st_rlx4(&g_hslot[buf][bid][lane], make_uint4(w0, w1, w2, cnt));
}

// Warp w polls chunks of its 8 producer CTAs (lanes 0..23: slot = w*8+lane/3,
// chunk = lane%3); data arrives WITH the successful poll. Stage into hstage
// (contiguous fp16 h[0..2047]; slot i owns h[i*16..i*16+16)).
__device__ __forceinline__ void poll_stage_h(int warp, int lane, unsigned base,
                                             unsigned j, __half* hstage) {
    if (lane < 24) {
        int slot = warp * 8 + lane / 3;
        int c    = lane - (lane / 3) * 3;
        const uint4* p = &g_hslot[j & 1][slot][c];
        uint4 v;
        do { v = ld_rlx4(p); } while (v.w - base < j);
        unsigned* dst = (unsigned*)((char*)hstage + slot * 32 + c * 12);
        dst[0] = v.x; dst[1] = v.y;
        if (c < 2) dst[2] = v.z;          // chunk 2 carries only h[12..15]
    }
}

// One-time: this CTA's 48 Whh rows (fp32, global) -> SMEM fp16 (row layout).
__device__ void load_w48(const float* __restrict__ W, __half* ws, int bid, int tid) {
    int warp = tid >> 5, lane = tid & 31;
#pragma unroll
    for (int rr = 0; rr < RPW; rr++) {
        int r48  = warp * RPW + rr;
        int grow = (r48 >> 4) * HID + bid * UPB + (r48 & 15);
        const float4* src = (const float4*)(W + (size_t)grow * HID);
#pragma unroll
        for (int c = 0; c < 16; c++) {
            float4 v = __ldg(&src[lane + c * 32]);
            union { __half2 h[2]; uint2 u; } cv;
            cv.h[0] = __floats2half2_rn(v.x, v.y);
            cv.h[1] = __floats2half2_rn(v.z, v.w);
            *(uint2*)&ws[(size_t)r48 * HID + (lane + c * 32) * 4] = cv.u;
        }
    }
}

// 48-row x 2048 matvec, fp16 weights+h in SMEM, HFMA2 with fp32 flush / 16.
__device__ __forceinline__ void matvec48_h2(const __half* __restrict__ ws,
                                            const __half2* __restrict__ hp,
                                            float* gh_s, const float* bhh_s,
                                            int tid) {
    int warp = tid >> 5, lane = tid & 31;
    float acc[RPW] = {0.f, 0.f, 0.f};
#pragma unroll
    for (int c = 0; c < 8; c += 2) {
        int g0 = (c * 32 + lane) * 4;          // half2 index
        int g1 = ((c + 1) * 32 + lane) * 4;
        uint4 hu0 = *(const uint4*)(hp + g0);
        uint4 hu1 = *(const uint4*)(hp + g1);
        __half2 h0 = *(__half2*)&hu0.x, h1 = *(__half2*)&hu0.y;
        __half2 h2 = *(__half2*)&hu0.z, h3 = *(__half2*)&hu0.w;
        __half2 h4 = *(__half2*)&hu1.x, h5 = *(__half2*)&hu1.y;
        __half2 h6 = *(__half2*)&hu1.z, h7 = *(__half2*)&hu1.w;
#pragma unroll
        for (int rr = 0; rr < RPW; rr++) {
            const __half2* wrow =
                (const __half2*)(ws + (size_t)(warp * RPW + rr) * HID);
            uint4 w0 = *(const uint4*)(wrow + g0);
            uint4 w1 = *(const uint4*)(wrow + g1);
            __half2 s = __hmul2(*(__half2*)&w0.x, h0);
            s = __hfma2(*(__half2*)&w0.y, h1, s);
            s = __hfma2(*(__half2*)&w0.z, h2, s);
            s = __hfma2(*(__half2*)&w0.w, h3, s);
            s = __hfma2(*(__half2*)&w1.x, h4, s);
            s = __hfma2(*(__half2*)&w1.y, h5, s);
            s = __hfma2(*(__half2*)&w1.z, h6, s);
            s = __hfma2(*(__half2*)&w1.w, h7, s);
            float2 f = __half22float2(s);
            acc[rr] += f.x + f.y;
        }
    }
#pragma unroll
    for (int rr = 0; rr < RPW; rr++) {
        float s = warp_sum(acc[rr]);
        if (lane == 0) gh_s[warp * RPW + rr] = s + bhh_s[warp * RPW + rr];
    }
}

// ---------------- fp32 -> fp16 converters -----------------------------------
__global__ void __launch_bounds__(256) conv_x_kernel(const float* __restrict__ src) {
    int i = blockIdx.x * blockDim.x + threadIdx.x;   // float4 index
    if (i < SEQ * INSZ / 4) {
        float4 v = __ldg((const float4*)src + i);
        union { __half2 h[2]; uint2 u; } cv;
        cv.h[0] = __floats2half2_rn(v.x, v.y);
        cv.h[1] = __floats2half2_rn(v.z, v.w);
        ((uint2*)g_Xh)[i] = cv.u;
    }
}
__global__ void __launch_bounds__(256) conv_w_kernel(const float* __restrict__ src) {
    int i = blockIdx.x * blockDim.x + threadIdx.x;
    if (i < G3 * INSZ / 4) {
        float4 v = __ldg((const float4*)src + i);
        union { __half2 h[2]; uint2 u; } cv;
        cv.h[0] = __floats2half2_rn(v.x, v.y);
        cv.h[1] = __floats2half2_rn(v.z, v.w);
        ((uint2*)g_Wh)[i] = cv.u;
    }
}
__global__ void __launch_bounds__(256) conv_wout_kernel(const float* __restrict__ src) {
    int i = blockIdx.x * blockDim.x + threadIdx.x;
    if (i < OUTSZ * HID / 4) {
        float4 v = __ldg((const float4*)src + i);
        union { __half2 h[2]; uint2 u; } cv;
        cv.h[0] = __floats2half2_rn(v.x, v.y);
        cv.h[1] = __floats2half2_rn(v.z, v.w);
        ((uint2*)g_Woh)[i] = cv.u;
    }
}

// ---------------- kernel 1: GI = X @ Wih^T (tensor cores, fp32 accum) -------
#define KC 32
__global__ void __launch_bounds__(256) gemm_wmma_kernel() {
    __shared__ __half As[128][KC + 8];
    __shared__ __half Bs[128][KC + 8];

    int m0 = blockIdx.y * 128, n0 = blockIdx.x * 128;
    int t = threadIdx.x;
    int wid = t >> 5;
    int wm = wid & 1, wn = wid >> 1;     // warp tile: 64(M) x 32(N)

    wmma::fragment<wmma::accumulator, 16, 16, 16, float> c[4][2];
#pragma unroll
    for (int i = 0; i < 4; i++)
#pragma unroll
        for (int j = 0; j < 2; j++) wmma::fill_fragment(c[i][j], 0.f);

    int lrow = t >> 1;
    int lseg = (t & 1) * 16;

    for (int k0 = 0; k0 < INSZ; k0 += KC) {
        const uint4* ap = (const uint4*)(g_Xh + (size_t)(m0 + lrow) * INSZ + k0 + lseg);
        const uint4* bp = (const uint4*)(g_Wh + (size_t)(n0 + lrow) * INSZ + k0 + lseg);
        uint4 a0 = ap[0], a1 = ap[1];
        uint4 b0 = bp[0], b1 = bp[1];
        __syncthreads();
        *(uint4*)&As[lrow][lseg]     = a0;
        *(uint4*)&As[lrow][lseg + 8] = a1;
        *(uint4*)&Bs[lrow][lseg]     = b0;
        *(uint4*)&Bs[lrow][lseg + 8] = b1;
        __syncthreads();
#pragma unroll
        for (int kk = 0; kk < KC; kk += 16) {
            wmma::fragment<wmma::matrix_a, 16, 16, 16, __half, wmma::row_major> af[4];
            wmma::fragment<wmma::matrix_b, 16, 16, 16, __half, wmma::col_major> bf[2];
#pragma unroll
            for (int i = 0; i < 4; i++)
                wmma::load_matrix_sync(af[i], &As[wm * 64 + i * 16][kk], KC + 8);
#pragma unroll
            for (int j = 0; j < 2; j++)
                wmma::load_matrix_sync(bf[j], &Bs[wn * 32 + j * 16][kk], KC + 8);
#pragma unroll
            for (int i = 0; i < 4; i++)
#pragma unroll
                for (int j = 0; j < 2; j++)
                    wmma::mma_sync(c[i][j], af[i], bf[j], c[i][j]);
        }
    }
#pragma unroll
    for (int i = 0; i < 4; i++)
#pragma unroll
        for (int j = 0; j < 2; j++)
            wmma::store_matrix_sync(
                &g_GI[(size_t)(m0 + wm * 64 + i * 16) * G3 + n0 + wn * 32 + j * 16],
                c[i][j], G3, wmma::mem_row_major);
}

// ---------------- kernel 2: persistent encoder + decoder --------------------
__global__ void __launch_bounds__(NT, 1) rnn_kernel(
    const float* __restrict__ enc_Whh, const float* __restrict__ enc_bih,
    const float* __restrict__ enc_bhh,
    const float* __restrict__ dec_Wih, const float* __restrict__ dec_Whh,
    const float* __restrict__ dec_bih, const float* __restrict__ dec_bhh,
    const float* __restrict__ b_out,
    float* __restrict__ out) {

    extern __shared__ char dyn[];
    __half* ws     = (__half*)dyn;                              // 192KB weights
    __half* hstage = (__half*)(dyn + RPB * HID * sizeof(__half));   // 4KB h

    __shared__ float gh_s[RPB];
    __shared__ float bhh_s[RPB];
    __shared__ float bih_s[RPB];
    __shared__ float ls[ORPB];
    __shared__ float red_s[3];          // gmax, lse, idx-as-bits

    int bid = blockIdx.x, tid = threadIdx.x;
    int warp = tid >> 5, lane = tid & 31;

    // base counters: the later of the two parity buffers' counters (all CTAs
    // publish the same count per launch, so bases are globally consistent).
    unsigned base  = later_u(ld_rlx4(&g_hslot[0][bid][0]).w,
                             ld_rlx4(&g_hslot[1][bid][0]).w);
    unsigned base2 = later_u(ld_rlx4(&g_pslot[0][bid]).w,
                             ld_rlx4(&g_pslot[1][bid]).w);

    // one-time: encoder Whh slice -> SMEM fp16; biases -> SMEM
    load_w48(enc_Whh, ws, bid, tid);
    if (tid < RPB) {
        int grow = (tid >> 4) * HID + bid * UPB + (tid & 15);
        bhh_s[tid] = enc_bhh[grow];
        bih_s[tid] = enc_bih[grow];
    }

    float h_reg = 0.f;                  // lane u<16 of warp 0 owns h[bid*16+u]
    unsigned j = 1;

    // publish initial h = 0 with counter base+1 (parity 1)
    if (warp == 0)
        publish_h(bid, lane, __half_as_ushort(__float2half(0.f)), base + 1, 1);

    // ---------------- encoder: 512 sequential GRU steps ----------------
    for (int t = 0; t < SEQ; t++) {
        float gi0 = 0.f, gi1 = 0.f, gi2 = 0.f;
        if (warp == 0 && lane < UPB) {  // prefetch gi (independent of h)
            const float* gi = g_GI + (size_t)t * G3 + bid * UPB + lane;
            gi0 = __ldg(gi); gi1 = __ldg(gi + HID); gi2 = __ldg(gi + 2 * HID);
        }
        poll_stage_h(warp, lane, base, j, hstage);
        __syncthreads();                        // full h staged
        matvec48_h2(ws, (const __half2*)hstage, gh_s, bhh_s, tid);
        __syncthreads();                        // gh_s ready
        if (warp == 0) {
            if (lane < UPB) {
                float r = sigmoidf_(gi0 + bih_s[lane]      + gh_s[lane]);
                float z = sigmoidf_(gi1 + bih_s[16 + lane] + gh_s[16 + lane]);
                float n = tanhf(    gi2 + bih_s[32 + lane]
                                        + r * gh_s[32 + lane]);
                h_reg = (1.f - z) * n + z * h_reg;
            }
            publish_h(bid, lane, __half_as_ushort(__float2half(h_reg)),
                      base + j + 1, (j + 1) & 1);
        }
        j++;
    }

    // ---------------- decoder: swap SMEM weights to dec_Whh ----------------
    __syncthreads();                    // warp0 gates done before bias swap
    load_w48(dec_Whh, ws, bid, tid);
    if (tid < RPB) {
        int grow = (tid >> 4) * HID + bid * UPB + (tid & 15);
        bhh_s[tid] = dec_bhh[grow];
    }

    int prev_idx = -1;     // first x is the zero vector
    for (int s = 0; s < STEPS; s++) {
        float gi0 = 0.f, gi1 = 0.f, gi2 = 0.f;
        if (warp == 0 && lane < UPB) {
            int u = bid * UPB + lane;
            gi0 = dec_bih[u];
            gi1 = dec_bih[HID + u];
            gi2 = dec_bih[2 * HID + u];
            if (prev_idx >= 0) {
                gi0 += __ldg(&dec_Wih[(size_t)u * INSZ + prev_idx]);
                gi1 += __ldg(&dec_Wih[(size_t)(HID + u) * INSZ + prev_idx]);
                gi2 += __ldg(&dec_Wih[(size_t)(2 * HID + u) * INSZ + prev_idx]);
            }
        }
        poll_stage_h(warp, lane, base, j, hstage);
        __syncthreads();
        matvec48_h2(ws, (const __half2*)hstage, gh_s, bhh_s, tid);
        __syncthreads();
        if (warp == 0) {
            if (lane < UPB) {
                float r = sigmoidf_(gi0 + gh_s[lane]);
                float z = sigmoidf_(gi1 + gh_s[16 + lane]);
                float n = tanhf(    gi2 + r * gh_s[32 + lane]);
                h_reg = (1.f - z) * n + z * h_reg;
            }
            publish_h(bid, lane, __half_as_ushort(__float2half(h_reg)),
                      base + j + 1, (j + 1) & 1);
        }
        j++;

        // stage h^(new) for logits (same self-sync poll)
        poll_stage_h(warp, lane, base, j, hstage);
        __syncthreads();

        // logits: 16 warps x 2 rows of fp16 W_out against SMEM h
        {
            const __half2* hp = (const __half2*)hstage;
            uint4 hreg[8];
#pragma unroll
            for (int c = 0; c < 8; c++)
                hreg[c] = *(const uint4*)(hp + (c * 32 + lane) * 4);
#pragma unroll
            for (int rr = 0; rr < 2; rr++) {
                int rl = warp * 2 + rr;
                int grow = bid * ORPB + rl;
                const uint4* wrow = (const uint4*)(g_Woh + (size_t)grow * HID);
                float acc = 0.f;
#pragma unroll
                for (int c = 0; c < 8; c++) {
                    uint4 w = __ldg(&wrow[lane + c * 32]);
                    __half2 sh = __hmul2(*(__half2*)&w.x, *(__half2*)&hreg[c].x);
                    sh = __hfma2(*(__half2*)&w.y, *(__half2*)&hreg[c].y, sh);
                    sh = __hfma2(*(__half2*)&w.z, *(__half2*)&hreg[c].z, sh);
                    sh = __hfma2(*(__half2*)&w.w, *(__half2*)&hreg[c].w, sh);
                    float2 f = __half22float2(sh);
                    acc += f.x + f.y;
                }
                acc = warp_sum(acc);
                if (lane == 0) ls[rl] = acc + b_out[grow];
            }
        }
        __syncthreads();                // ls ready

        // warp 0: publish self-sync pack chunk; poll all; reduce
        if (warp == 0) {
            float v = ls[lane];
            unsigned long long pack =
                ((unsigned long long)f2sortable(v) << 32) |
                (unsigned long long)(0xFFFFFFFFu - (unsigned)(bid * ORPB + lane));
#pragma unroll
            for (int o = 16; o; o >>= 1) {
                unsigned long long other = __shfl_xor_sync(0xffffffffu, pack, o);
                pack = other > pack ? other : pack;
            }
            float lmax = sortable2f((unsigned)(pack >> 32));
            float e = warp_sum(expf(v - lmax));
            unsigned s1 = s + 1;
            if (lane == 0)
                st_rlx4(&g_pslot[s1 & 1][bid],
                        make_uint4((unsigned)(pack & 0xFFFFFFFFull),
                                   (unsigned)(pack >> 32),
                                   __float_as_uint(e), base2 + s1));
            unsigned long long pk[4];
            float lsm[4];
#pragma unroll
            for (int i = 0; i < 4; i++) {
                const uint4* p = &g_pslot[s1 & 1][lane + i * 32];
                uint4 v2;
                do { v2 = ld_rlx4(p); } while (v2.w - base2 < s1);
                pk[i]  = ((unsigned long long)v2.y << 32) | v2.x;
                lsm[i] = __uint_as_float(v2.z);
            }
            unsigned long long m = pk[0];
#pragma unroll
            for (int i = 1; i < 4; i++) m = pk[i] > m ? pk[i] : m;
#pragma unroll
            for (int o = 16; o; o >>= 1) {
                unsigned long long other = __shfl_xor_sync(0xffffffffu, m, o);
                m = other > m ? other : m;
            }
            float gmax = sortable2f((unsigned)(m >> 32));
            float part = 0.f;
#pragma unroll
            for (int i = 0; i < 4; i++)
                part += lsm[i] * expf(sortable2f((unsigned)(pk[i] >> 32)) - gmax);
            part = warp_sum(part);
            if (lane == 0) {
                red_s[0] = gmax;
                red_s[1] = logf(part);
                red_s[2] = __uint_as_float(
                    0xFFFFFFFFu - (unsigned)(m & 0xFFFFFFFFull));
            }
        }
        __syncthreads();                // red_s ready
        float gmax = red_s[0], lse = red_s[1];
        prev_idx = (int)__float_as_uint(red_s[2]);
        if (tid < ORPB)
            out[(size_t)s * OUTSZ + bid * ORPB + tid] = ls[tid] - gmax - lse;
    }
}

// ---------------- launch ----------------------------------------------------
extern "C" void kernel_launch(void* const* d_in, const int* in_sizes, int n_in,
                              void* d_out, int out_size) {
    const float* input   = (const float*)d_in[0];
    const float* enc_Wih = (const float*)d_in[1];
    const float* enc_Whh = (const float*)d_in[2];
    const float* enc_bih = (const float*)d_in[3];
    const float* enc_bhh = (const float*)d_in[4];
    const float* dec_Wih = (const float*)d_in[5];
    const float* dec_Whh = (const float*)d_in[6];
    const float* dec_bih = (const float*)d_in[7];
    const float* dec_bhh = (const float*)d_in[8];
    const float* W_out   = (const float*)d_in[9];
    const float* b_out   = (const float*)d_in[10];
    float* out = (float*)d_out;

    static const int kDynSmem = RPB * HID * sizeof(__half)   // weights 192KB
                              + HID * sizeof(__half);        // h stage 4KB
    cudaFuncSetAttribute(rnn_kernel,
                         cudaFuncAttributeMaxDynamicSharedMemorySize, kDynSmem);

    conv_x_kernel<<<(SEQ * INSZ / 4 + 255) / 256, 256>>>(input);
    conv_w_kernel<<<(G3 * INSZ / 4 + 255) / 256, 256>>>(enc_Wih);
    conv_wout_kernel<<<(OUTSZ * HID / 4 + 255) / 256, 256>>>(W_out);

    dim3 g1(G3 / 128, SEQ / 128);   // 48 x 4
    gemm_wmma_kernel<<<g1, 256>>>();

    rnn_kernel<<<NB, NT, kDynSmem>>>(enc_Whh, enc_bih, enc_bhh,
                                     dec_Wih, dec_Whh, dec_bih, dec_bhh,
                                     b_out, out);
}